// round 1
// baseline (speedup 1.0000x reference)
#include <cuda_runtime.h>

// Problem constants (fixed by the dataset): B=512, T=512, L=128
#define BB 512
#define TT 512
#define LL 128

__device__ __forceinline__ unsigned long long pack2(float x, float y) {
    unsigned long long r;
    asm("mov.b64 %0, {%1, %2};" : "=l"(r) : "f"(x), "f"(y));
    return r;
}

// Packed f32x2 FMA (FFMA2) — 2x fp32 throughput vs 3-reg FFMA on sm_103a.
__device__ __forceinline__ unsigned long long fma2(unsigned long long a,
                                                   unsigned long long b,
                                                   unsigned long long c) {
    unsigned long long d;
    asm("fma.rn.f32x2 %0, %1, %2, %3;" : "=l"(d) : "l"(a), "l"(b), "l"(c));
    return d;
}

// One CTA per batch element b. 128 threads.
//   warp w (=tid>>5) owns the i-slice  i in [32w, 32w+32)
//   lane  (=tid&31)  owns the j-quad   j in [4*lane, 4*lane+4)
// E = exp(transfer) lives in registers: 64 f32x2 per thread.
__global__ __launch_bounds__(128, 3) void crf_kernel(
    const float* __restrict__ feats,     // [B, T, L]
    const float* __restrict__ transfer,  // [L, L]
    const int*   __restrict__ target,    // [B, T]
    const int*   __restrict__ startp,    // scalar (may be null -> L-2)
    const int*   __restrict__ stopp,     // scalar (may be null -> L-1)
    float*       __restrict__ out)       // [B]
{
    __shared__ unsigned long long pdup[LL];   // P duplicated into both f32x2 halves
    __shared__ unsigned long long sred64[4 * LL / 2]; // 4 warps x 128 floats of partials
    __shared__ float smax[4];
    __shared__ float ssum[4];
    __shared__ float sg[4];

    const int b    = blockIdx.x;
    const int tid  = threadIdx.x;
    const int lane = tid & 31;
    const int wid  = tid >> 5;

    const int start = startp ? *startp : (LL - 2);
    const int stop  = stopp  ? *stopp  : (LL - 1);

    const float* fb = feats  + (size_t)b * TT * LL;
    const int*   tb = target + (size_t)b * TT;

    // ---- Load E = exp(transfer) tile into registers ----
    unsigned long long e0[32], e1[32];
#pragma unroll
    for (int k = 0; k < 32; k++) {
        const int i = (wid << 5) + k;
        const float4 tv = *reinterpret_cast<const float4*>(transfer + i * LL + (lane << 2));
        e0[k] = pack2(__expf(tv.x), __expf(tv.y));
        e1[k] = pack2(__expf(tv.z), __expf(tv.w));
    }

    // ---- Gold-path partial sums (emit + trans), strided over t ----
    float g = 0.f;
    for (int t = 1 + tid; t < TT; t += 128) {
        const int tg = tb[t];
        const int pr = (t == 1) ? start : tb[t - 1];
        g += fb[t * LL + tg] + transfer[pr * LL + tg];
    }

    // ---- prev0 = feats[:,1,:] + transfer[start,:] ----
    float prev = fb[1 * LL + tid] + transfer[start * LL + tid];

    // ---- Main scan: t = 2 .. T-1 ----
    float fcur = fb[2 * LL + tid];
    for (int t = 2; t < TT; t++) {
        // prefetch next step's feature row (clamped dummy on last iter)
        const int tn = (t + 1 < TT) ? (t + 1) : (TT - 1);
        const float fnext = fb[tn * LL + tid];

        const float v = prev + fcur;

        // block-wide max of v (stabilizer)
        float m = v;
#pragma unroll
        for (int off = 16; off; off >>= 1)
            m = fmaxf(m, __shfl_xor_sync(0xffffffffu, m, off));
        if (lane == 0) smax[wid] = m;
        __syncthreads();
        m = fmaxf(fmaxf(smax[0], smax[1]), fmaxf(smax[2], smax[3]));

        const float p = __expf(v - m);
        pdup[tid] = pack2(p, p);
        __syncthreads();

        // S_j partials over this warp's i-slice: 32 LDS.64 (broadcast) + 64 FFMA2
        unsigned long long a0 = 0ull, a1 = 0ull;
        const unsigned long long* pd = pdup + (wid << 5);
#pragma unroll
        for (int k = 0; k < 32; k++) {
            const unsigned long long pk = pd[k];
            a0 = fma2(pk, e0[k], a0);
            a1 = fma2(pk, e1[k], a1);
        }

        // partials: sred_f[wid*128 + 4*lane + {0..3}]
        unsigned long long* s64 = sred64 + (wid << 6) + (lane << 1);
        s64[0] = a0;
        s64[1] = a1;
        __syncthreads();

        const float* sred = reinterpret_cast<const float*>(sred64);
        const float S = sred[tid] + sred[LL + tid] + sred[2 * LL + tid] + sred[3 * LL + tid];
        prev = m + __logf(S);
        fcur = fnext;
    }

    // ---- sentence_score = LSE_j(prev_j + transfer[j, stop]) ----
    const float v2 = prev + transfer[tid * LL + stop];
    float m2 = v2;
#pragma unroll
    for (int off = 16; off; off >>= 1)
        m2 = fmaxf(m2, __shfl_xor_sync(0xffffffffu, m2, off));
    if (lane == 0) smax[wid] = m2;
    __syncthreads();
    m2 = fmaxf(fmaxf(smax[0], smax[1]), fmaxf(smax[2], smax[3]));

    float es = __expf(v2 - m2);
    float gg = g;
#pragma unroll
    for (int off = 16; off; off >>= 1) {
        es += __shfl_xor_sync(0xffffffffu, es, off);
        gg += __shfl_xor_sync(0xffffffffu, gg, off);
    }
    if (lane == 0) { ssum[wid] = es; sg[wid] = gg; }
    __syncthreads();

    if (tid == 0) {
        const float Ssum = ssum[0] + ssum[1] + ssum[2] + ssum[3];
        const float sentence = m2 + __logf(Ssum);
        const float gsum = sg[0] + sg[1] + sg[2] + sg[3];
        const float emit0 = fb[start];  // feats[b, 0, start]
        out[b] = sentence - __expf(emit0 + gsum);
    }
}

extern "C" void kernel_launch(void* const* d_in, const int* in_sizes, int n_in,
                              void* d_out, int out_size) {
    const float* feats    = (const float*)d_in[0];
    const float* transfer = (const float*)d_in[1];
    const int*   target   = (const int*)d_in[2];
    const int*   startp   = (n_in >= 4) ? (const int*)d_in[3] : nullptr;
    const int*   stopp    = (n_in >= 5) ? (const int*)d_in[4] : nullptr;

    crf_kernel<<<BB, 128>>>(feats, transfer, target, startp, stopp, (float*)d_out);
}